// round 4
// baseline (speedup 1.0000x reference)
#include <cuda_runtime.h>
#include <cuda_fp16.h>

#define BB 128
#define LL 512
#define KN 8
#define DD 300
#define CC 14
#define LCHUNK 64
#define NCHUNK (LL / LCHUNK)   // 8
#define NROWS 4905             // NUM_NODES + 1
#define RSTRIDE 320            // halves per row: 640B = 5 x 128B sectors
#define NH2 (NROWS * RSTRIDE / 2)   // 784800 half2 elements

// fp16 copy of R, row-padded for sector alignment
__device__ __half2 g_Rh2[NH2];
// Deterministic partial-sum scratch: [chunk][b][d]
__device__ float g_part[NCHUNK * BB * DD];
// Per-batch completion counters (reset by convert_kernel every replay)
__device__ unsigned int g_counter[BB];

__global__ __launch_bounds__(256)
void convert_kernel(const float* __restrict__ R)
{
    // Reset counters (runs before pool in launch order)
    if (blockIdx.x == 0 && threadIdx.x < BB)
        g_counter[threadIdx.x] = 0u;

    const int stride = gridDim.x * blockDim.x;
    for (int i = blockIdx.x * blockDim.x + threadIdx.x; i < NH2; i += stride) {
        const int row = i / (RSTRIDE / 2);
        const int col = (i - row * (RSTRIDE / 2)) * 2;
        __half2 h = __half2half2(__float2half(0.f));
        if (col < DD) {   // DD even -> pair fully valid
            const float2 v = *(const float2*)&R[row * DD + col];
            h = __floats2half2_rn(v.x, v.y);
        }
        g_Rh2[i] = h;
    }
}

__global__ __launch_bounds__(160)
void gnn_pool_kernel(const int* __restrict__ master,
                     const int* __restrict__ slave,
                     const int* __restrict__ edge,
                     const float* __restrict__ E,
                     const float* __restrict__ Ngate,
                     const float* __restrict__ W,
                     const float* __restrict__ bias,
                     float* __restrict__ out)
{
    const int b     = blockIdx.y;
    const int chunk = blockIdx.x;
    const int tid   = threadIdx.x;

    __shared__ int   s_node[LCHUNK * KN];
    __shared__ float s_e[LCHUNK * KN];
    __shared__ int   s_m[LCHUNK];
    __shared__ float s_g[LCHUNK];

    const int base = b * LL + chunk * LCHUNK;

    // Cooperative metadata load: 512 slaves/edges + 64 masters/gates
    for (int i = tid; i < LCHUNK * KN; i += 160) {
        const int pos = base + (i >> 3);
        const int k   = i & 7;
        s_node[i] = slave[pos * KN + k];
        s_e[i]    = E[edge[pos * KN + k]];
    }
    if (tid < LCHUNK) {
        const int m = master[base + tid];
        s_m[tid] = m;
        s_g[tid] = Ngate[m];
    }
    __syncthreads();

    const bool active = (tid < 150);   // 150 half2 lanes cover 300 dims
    float2 acc = make_float2(0.f, 0.f);

    if (active) {
        #pragma unroll 2
        for (int li = 0; li < LCHUNK; ++li) {
            const int*   np = &s_node[li * KN];
            const float* ep = &s_e[li * KN];
            const int    m  = s_m[li];
            const float  g  = s_g[li];

            float2 f = __half22float2(g_Rh2[np[0] * (RSTRIDE / 2) + tid]);
            float mx0 = f.x * ep[0];
            float mx1 = f.y * ep[0];
            #pragma unroll
            for (int k = 1; k < KN; ++k) {
                float2 fk = __half22float2(g_Rh2[np[k] * (RSTRIDE / 2) + tid]);
                mx0 = fmaxf(mx0, fk.x * ep[k]);
                mx1 = fmaxf(mx1, fk.y * ep[k]);
            }
            float2 fm = __half22float2(g_Rh2[m * (RSTRIDE / 2) + tid]);

            acc.x += mx0 + g * (fm.x - mx0);
            acc.y += mx1 + g * (fm.y - mx1);
        }
        float2* outp = (float2*)&g_part[(chunk * BB + b) * DD];
        outp[tid] = acc;
    }

    // ---- threadfence reduction: last block for batch b runs the head ----
    __threadfence();
    __shared__ bool isLast;
    if (tid == 0)
        isLast = (atomicAdd(&g_counter[b], 1u) == NCHUNK - 1);
    __syncthreads();
    if (!isLast) return;

    __shared__ float sx[DD];
    __shared__ float sh[CC];

    // Reduce the 8 partials -> X[b][:] (L1-bypassing loads; fixed order)
    if (active) {
        float2 s = make_float2(0.f, 0.f);
        #pragma unroll
        for (int c = 0; c < NCHUNK; ++c) {
            const float* p = &g_part[(c * BB + b) * DD + tid * 2];
            s.x += __ldcg(p);
            s.y += __ldcg(p + 1);
        }
        sx[tid * 2]     = s.x;
        sx[tid * 2 + 1] = s.y;
    }
    __syncthreads();

    // FC: 5 warps, warp w handles classes w*3 .. w*3+2 (15 slots, 14 used)
    {
        const int wid  = tid >> 5;
        const int lane = tid & 31;
        #pragma unroll
        for (int j = 0; j < 3; ++j) {
            const int c = wid * 3 + j;
            if (c < CC) {
                float s = 0.f;
                for (int d = lane; d < DD; d += 32)
                    s += sx[d] * W[c * DD + d];
                #pragma unroll
                for (int off = 16; off; off >>= 1)
                    s += __shfl_down_sync(0xffffffffu, s, off);
                if (lane == 0)
                    sh[c] = fmaxf(s + bias[c], 0.f);
            }
        }
    }
    __syncthreads();

    // Softmax over 14 classes
    if (tid == 0) {
        float m = sh[0];
        #pragma unroll
        for (int c = 1; c < CC; ++c) m = fmaxf(m, sh[c]);
        float e[CC];
        float sum = 0.f;
        #pragma unroll
        for (int c = 0; c < CC; ++c) { e[c] = expf(sh[c] - m); sum += e[c]; }
        const float inv = 1.f / sum;
        #pragma unroll
        for (int c = 0; c < CC; ++c) out[b * CC + c] = e[c] * inv;
    }
}

extern "C" void kernel_launch(void* const* d_in, const int* in_sizes, int n_in,
                              void* d_out, int out_size)
{
    const int*   master = (const int*)  d_in[0];
    const int*   slave  = (const int*)  d_in[1];
    const int*   edge   = (const int*)  d_in[2];
    const float* R      = (const float*)d_in[3];
    const float* E      = (const float*)d_in[4];
    const float* Ngate  = (const float*)d_in[5];
    const float* W      = (const float*)d_in[6];
    const float* bias   = (const float*)d_in[7];
    float* out = (float*)d_out;

    convert_kernel<<<512, 256>>>(R);
    gnn_pool_kernel<<<dim3(NCHUNK, BB), 160>>>(master, slave, edge, E, Ngate,
                                               W, bias, out);
}

// round 5
// speedup vs baseline: 1.0867x; 1.0867x over previous
#include <cuda_runtime.h>
#include <cuda_fp16.h>

#define BB 128
#define LL 512
#define KN 8
#define DD 300
#define CC 14
#define LCHUNK 32
#define NCHUNK (LL / LCHUNK)   // 16
#define NROWS 4905             // NUM_NODES + 1
#define RSTRIDE 320            // halves per row: 640B = 5 x 128B sectors
#define NH2 (NROWS * RSTRIDE / 2)

// fp16 copy of R, row-padded for sector alignment
__device__ __half2 g_Rh2[NH2];
// Deterministic partial-sum scratch: [chunk][b][d]
__device__ float g_part[NCHUNK * BB * DD];

__global__ __launch_bounds__(256)
void convert_kernel(const float* __restrict__ R)
{
    const int stride = gridDim.x * blockDim.x;
    for (int i = blockIdx.x * blockDim.x + threadIdx.x; i < NH2; i += stride) {
        const int row = i / (RSTRIDE / 2);
        const int col = (i - row * (RSTRIDE / 2)) * 2;
        __half2 h = __half2half2(__float2half(0.f));
        if (col < DD) {   // DD even -> pair fully valid
            const float2 v = *(const float2*)&R[row * DD + col];
            h = __floats2half2_rn(v.x, v.y);
        }
        g_Rh2[i] = h;
    }
}

__global__ __launch_bounds__(160)
void gnn_pool_kernel(const int* __restrict__ master,
                     const int* __restrict__ slave,
                     const int* __restrict__ edge,
                     const float* __restrict__ E,
                     const float* __restrict__ Ngate)
{
    const int b     = blockIdx.y;
    const int chunk = blockIdx.x;
    const int tid   = threadIdx.x;

    __shared__ int   s_node[LCHUNK * KN];
    __shared__ float s_e[LCHUNK * KN];
    __shared__ int   s_m[LCHUNK];
    __shared__ float s_g[LCHUNK];

    const int base = b * LL + chunk * LCHUNK;

    // Cooperative metadata load: 256 slaves/edges + 32 masters/gates
    for (int i = tid; i < LCHUNK * KN; i += 160) {
        const int pos = base + (i >> 3);
        const int k   = i & 7;
        s_node[i] = slave[pos * KN + k];
        s_e[i]    = E[edge[pos * KN + k]];
    }
    if (tid < LCHUNK) {
        const int m = master[base + tid];
        s_m[tid] = m;
        s_g[tid] = Ngate[m];
    }
    __syncthreads();

    if (tid >= 150) return;   // 150 half2 lanes cover 300 dims

    float2 acc = make_float2(0.f, 0.f);

    #pragma unroll 2
    for (int li = 0; li < LCHUNK; ++li) {
        const int*   np = &s_node[li * KN];
        const float* ep = &s_e[li * KN];
        const int    m  = s_m[li];
        const float  g  = s_g[li];

        float2 f = __half22float2(g_Rh2[np[0] * (RSTRIDE / 2) + tid]);
        float mx0 = f.x * ep[0];
        float mx1 = f.y * ep[0];
        #pragma unroll
        for (int k = 1; k < KN; ++k) {
            float2 fk = __half22float2(g_Rh2[np[k] * (RSTRIDE / 2) + tid]);
            mx0 = fmaxf(mx0, fk.x * ep[k]);
            mx1 = fmaxf(mx1, fk.y * ep[k]);
        }
        float2 fm = __half22float2(g_Rh2[m * (RSTRIDE / 2) + tid]);

        acc.x += mx0 + g * (fm.x - mx0);
        acc.y += mx1 + g * (fm.y - mx1);
    }

    float2* outp = (float2*)&g_part[(chunk * BB + b) * DD];
    outp[tid] = acc;
}

__global__ __launch_bounds__(448)
void head_kernel(const float* __restrict__ W,
                 const float* __restrict__ bias,
                 float* __restrict__ out)
{
    const int b    = blockIdx.x;
    const int tid  = threadIdx.x;
    const int wid  = tid >> 5;
    const int lane = tid & 31;

    __shared__ float sx[DD];
    __shared__ float sh[CC];

    // Reduce the 16 partials -> X[b][:]  (150 float2 lanes)
    if (tid < 150) {
        float2 s = make_float2(0.f, 0.f);
        #pragma unroll
        for (int c = 0; c < NCHUNK; ++c) {
            const float2 p = *(const float2*)&g_part[(c * BB + b) * DD + tid * 2];
            s.x += p.x;
            s.y += p.y;
        }
        sx[tid * 2]     = s.x;
        sx[tid * 2 + 1] = s.y;
    }
    __syncthreads();

    // One warp per class: h[c] = relu(X . W[c] + bias[c])
    if (wid < CC) {
        float s = 0.f;
        for (int d = lane; d < DD; d += 32)
            s += sx[d] * W[wid * DD + d];
        #pragma unroll
        for (int off = 16; off; off >>= 1)
            s += __shfl_down_sync(0xffffffffu, s, off);
        if (lane == 0)
            sh[wid] = fmaxf(s + bias[wid], 0.f);
    }
    __syncthreads();

    // Softmax over 14 classes
    if (tid == 0) {
        float m = sh[0];
        #pragma unroll
        for (int c = 1; c < CC; ++c) m = fmaxf(m, sh[c]);
        float e[CC];
        float sum = 0.f;
        #pragma unroll
        for (int c = 0; c < CC; ++c) { e[c] = expf(sh[c] - m); sum += e[c]; }
        const float inv = 1.f / sum;
        #pragma unroll
        for (int c = 0; c < CC; ++c) out[b * CC + c] = e[c] * inv;
    }
}

extern "C" void kernel_launch(void* const* d_in, const int* in_sizes, int n_in,
                              void* d_out, int out_size)
{
    const int*   master = (const int*)  d_in[0];
    const int*   slave  = (const int*)  d_in[1];
    const int*   edge   = (const int*)  d_in[2];
    const float* R      = (const float*)d_in[3];
    const float* E      = (const float*)d_in[4];
    const float* Ngate  = (const float*)d_in[5];
    const float* W      = (const float*)d_in[6];
    const float* bias   = (const float*)d_in[7];
    float* out = (float*)d_out;

    convert_kernel<<<512, 256>>>(R);
    gnn_pool_kernel<<<dim3(NCHUNK, BB), 160>>>(master, slave, edge, E, Ngate);
    head_kernel<<<BB, 448>>>(W, bias, out);
}

// round 6
// speedup vs baseline: 1.1634x; 1.0705x over previous
#include <cuda_runtime.h>
#include <cuda_fp16.h>

#define BB 128
#define LL 512
#define KN 8
#define DD 300
#define CC 14
#define LCHUNK 64
#define NCHUNK (LL / LCHUNK)   // 8
#define NROWS 4905             // NUM_NODES + 1
#define RSTRIDE 320            // halves per row: 640B = 5 x 128B sectors
#define RH2 (RSTRIDE / 2)      // 160 half2 per row
#define ROWS_PER_BLK 4

// fp16 copy of R, row-padded for sector alignment
__device__ __half2 g_Rh2[NROWS * RH2];
// Deterministic partial-sum scratch: [chunk][b][d]
__device__ float g_part[NCHUNK * BB * DD];

__global__ __launch_bounds__(160)
void convert_kernel(const float* __restrict__ R)
{
    const int t = threadIdx.x;
    const int row0 = blockIdx.x * ROWS_PER_BLK;

    #pragma unroll
    for (int j = 0; j < ROWS_PER_BLK; ++j) {
        const int row = row0 + j;
        if (row >= NROWS) return;
        __half2 h = __half2half2(__half(0));
        if (t < DD / 2) {
            const float2 v = *(const float2*)&R[row * DD + t * 2];
            h = __floats2half2_rn(v.x, v.y);
        }
        g_Rh2[row * RH2 + t] = h;
    }
}

__global__ __launch_bounds__(160)
void gnn_pool_kernel(const int* __restrict__ master,
                     const int* __restrict__ slave,
                     const int* __restrict__ edge,
                     const float* __restrict__ E,
                     const float* __restrict__ Ngate)
{
    const int b     = blockIdx.y;
    const int chunk = blockIdx.x;
    const int tid   = threadIdx.x;

    __shared__ int   s_node[LCHUNK * KN];   // pre-scaled to half2 offsets
    __shared__ float s_e[LCHUNK * KN];
    __shared__ int   s_m[LCHUNK];           // pre-scaled
    __shared__ float s_g[LCHUNK];

    const int base = b * LL + chunk * LCHUNK;

    // Cooperative metadata load: 512 slaves/edges + 64 masters/gates
    for (int i = tid; i < LCHUNK * KN; i += 160) {
        const int pos = base + (i >> 3);
        const int k   = i & 7;
        s_node[i] = slave[pos * KN + k] * RH2;
        s_e[i]    = E[edge[pos * KN + k]];
    }
    if (tid < LCHUNK) {
        const int m = master[base + tid];
        s_m[tid] = m * RH2;
        s_g[tid] = Ngate[m];
    }
    __syncthreads();

    if (tid >= 150) return;   // 150 half2 lanes cover 300 dims

    const __half2* Rbase = g_Rh2 + tid;
    float2 acc = make_float2(0.f, 0.f);

    #pragma unroll 2
    for (int li = 0; li < LCHUNK; ++li) {
        const int*   np = &s_node[li * KN];
        const float* ep = &s_e[li * KN];

        float2 f = __half22float2(Rbase[np[0]]);
        float mx0 = f.x * ep[0];
        float mx1 = f.y * ep[0];
        #pragma unroll
        for (int k = 1; k < KN; ++k) {
            float2 fk = __half22float2(Rbase[np[k]]);
            mx0 = fmaxf(mx0, fk.x * ep[k]);
            mx1 = fmaxf(mx1, fk.y * ep[k]);
        }
        float2 fm = __half22float2(Rbase[s_m[li]]);
        const float g = s_g[li];

        acc.x += mx0 + g * (fm.x - mx0);
        acc.y += mx1 + g * (fm.y - mx1);
    }

    float2* outp = (float2*)&g_part[(chunk * BB + b) * DD];
    outp[tid] = acc;
}

__global__ __launch_bounds__(448)
void head_kernel(const float* __restrict__ W,
                 const float* __restrict__ bias,
                 float* __restrict__ out)
{
    const int b    = blockIdx.x;
    const int tid  = threadIdx.x;
    const int wid  = tid >> 5;
    const int lane = tid & 31;

    __shared__ float sx[DD];
    __shared__ float sh[CC];

    // Reduce the 8 partials -> X[b][:]  (150 float2 lanes)
    if (tid < 150) {
        float2 s = make_float2(0.f, 0.f);
        #pragma unroll
        for (int c = 0; c < NCHUNK; ++c) {
            const float2 p = *(const float2*)&g_part[(c * BB + b) * DD + tid * 2];
            s.x += p.x;
            s.y += p.y;
        }
        sx[tid * 2]     = s.x;
        sx[tid * 2 + 1] = s.y;
    }
    __syncthreads();

    // One warp per class: h[c] = relu(X . W[c] + bias[c])
    if (wid < CC) {
        float s = 0.f;
        #pragma unroll
        for (int it = 0; it < 10; ++it) {
            const int d = lane + it * 32;
            if (d < DD) s += sx[d] * W[wid * DD + d];
        }
        #pragma unroll
        for (int off = 16; off; off >>= 1)
            s += __shfl_down_sync(0xffffffffu, s, off);
        if (lane == 0)
            sh[wid] = fmaxf(s + bias[wid], 0.f);
    }
    __syncthreads();

    // Softmax over 14 classes
    if (tid == 0) {
        float m = sh[0];
        #pragma unroll
        for (int c = 1; c < CC; ++c) m = fmaxf(m, sh[c]);
        float e[CC];
        float sum = 0.f;
        #pragma unroll
        for (int c = 0; c < CC; ++c) { e[c] = expf(sh[c] - m); sum += e[c]; }
        const float inv = 1.f / sum;
        #pragma unroll
        for (int c = 0; c < CC; ++c) out[b * CC + c] = e[c] * inv;
    }
}

extern "C" void kernel_launch(void* const* d_in, const int* in_sizes, int n_in,
                              void* d_out, int out_size)
{
    const int*   master = (const int*)  d_in[0];
    const int*   slave  = (const int*)  d_in[1];
    const int*   edge   = (const int*)  d_in[2];
    const float* R      = (const float*)d_in[3];
    const float* E      = (const float*)d_in[4];
    const float* Ngate  = (const float*)d_in[5];
    const float* W      = (const float*)d_in[6];
    const float* bias   = (const float*)d_in[7];
    float* out = (float*)d_out;

    convert_kernel<<<(NROWS + ROWS_PER_BLK - 1) / ROWS_PER_BLK, 160>>>(R);
    gnn_pool_kernel<<<dim3(NCHUNK, BB), 160>>>(master, slave, edge, E, Ngate);
    head_kernel<<<BB, 448>>>(W, bias, out);
}

// round 7
// speedup vs baseline: 1.1743x; 1.0094x over previous
#include <cuda_runtime.h>
#include <cuda_fp16.h>

#define BB 128
#define LL 512
#define KN 8
#define DD 300
#define CC 14
#define LCHUNK 64
#define NCHUNK (LL / LCHUNK)   // 8
#define NROWS 4905             // NUM_NODES + 1
#define RSTRIDE 320            // halves per row: 640B = 5 x 128B sectors
#define RH2 (RSTRIDE / 2)      // 160 half2 per row
#define CVT_ROWS 8

// fp16 copy of R, row-padded for sector alignment
__device__ __half2 g_Rh2[NROWS * RH2];
// Deterministic partial-sum scratch: [chunk][b][d]
__device__ float g_part[NCHUNK * BB * DD];

__global__ __launch_bounds__(160)
void convert_kernel(const float* __restrict__ R)
{
    const int t = threadIdx.x;
    const int row0 = blockIdx.x * CVT_ROWS;

    // All loads first (independent -> MLP=8), then all stores.
    float2 v[CVT_ROWS];
    const bool lane_ok = (t < DD / 2);
    #pragma unroll
    for (int j = 0; j < CVT_ROWS; ++j) {
        const int row = min(row0 + j, NROWS - 1);   // clamp, no divergent return
        v[j] = lane_ok ? *(const float2*)&R[row * DD + t * 2]
                       : make_float2(0.f, 0.f);
    }
    #pragma unroll
    for (int j = 0; j < CVT_ROWS; ++j) {
        const int row = row0 + j;
        if (row < NROWS)
            g_Rh2[row * RH2 + t] = __floats2half2_rn(v[j].x, v[j].y);
    }
}

__global__ __launch_bounds__(160)
void gnn_pool_kernel(const int* __restrict__ master,
                     const int* __restrict__ slave,
                     const int* __restrict__ edge,
                     const float* __restrict__ E,
                     const float* __restrict__ Ngate)
{
    const int b     = blockIdx.y;
    const int chunk = blockIdx.x;
    const int tid   = threadIdx.x;

    __shared__ __align__(16) int   s_node[LCHUNK * KN];  // pre-scaled half2 offsets
    __shared__ __align__(16) float s_e[LCHUNK * KN];
    __shared__ int   s_m[LCHUNK];                        // pre-scaled
    __shared__ float s_g[LCHUNK];

    const int base = b * LL + chunk * LCHUNK;

    // Cooperative metadata load: 512 slaves/edges + 64 masters/gates
    for (int i = tid; i < LCHUNK * KN; i += 160) {
        const int pos = base + (i >> 3);
        const int k   = i & 7;
        s_node[i] = slave[pos * KN + k] * RH2;
        s_e[i]    = E[edge[pos * KN + k]];
    }
    if (tid < LCHUNK) {
        const int m = master[base + tid];
        s_m[tid] = m * RH2;
        s_g[tid] = Ngate[m];
    }
    __syncthreads();

    if (tid >= 150) return;   // 150 half2 lanes cover 300 dims

    const __half2* Rbase = g_Rh2 + tid;
    float2 acc = make_float2(0.f, 0.f);

    #pragma unroll 4
    for (int li = 0; li < LCHUNK; ++li) {
        // Vectorized metadata reads: 4x LDS.128 instead of 16x LDS.32
        const int4   n0 = *(const int4*)  &s_node[li * KN];
        const int4   n1 = *(const int4*)  &s_node[li * KN + 4];
        const float4 e0 = *(const float4*)&s_e[li * KN];
        const float4 e1 = *(const float4*)&s_e[li * KN + 4];

        const float2 f0 = __half22float2(Rbase[n0.x]);
        const float2 f1 = __half22float2(Rbase[n0.y]);
        const float2 f2 = __half22float2(Rbase[n0.z]);
        const float2 f3 = __half22float2(Rbase[n0.w]);
        const float2 f4 = __half22float2(Rbase[n1.x]);
        const float2 f5 = __half22float2(Rbase[n1.y]);
        const float2 f6 = __half22float2(Rbase[n1.z]);
        const float2 f7 = __half22float2(Rbase[n1.w]);
        const float2 fm = __half22float2(Rbase[s_m[li]]);

        float mx0 = f0.x * e0.x;
        float mx1 = f0.y * e0.x;
        mx0 = fmaxf(mx0, f1.x * e0.y);  mx1 = fmaxf(mx1, f1.y * e0.y);
        mx0 = fmaxf(mx0, f2.x * e0.z);  mx1 = fmaxf(mx1, f2.y * e0.z);
        mx0 = fmaxf(mx0, f3.x * e0.w);  mx1 = fmaxf(mx1, f3.y * e0.w);
        mx0 = fmaxf(mx0, f4.x * e1.x);  mx1 = fmaxf(mx1, f4.y * e1.x);
        mx0 = fmaxf(mx0, f5.x * e1.y);  mx1 = fmaxf(mx1, f5.y * e1.y);
        mx0 = fmaxf(mx0, f6.x * e1.z);  mx1 = fmaxf(mx1, f6.y * e1.z);
        mx0 = fmaxf(mx0, f7.x * e1.w);  mx1 = fmaxf(mx1, f7.y * e1.w);

        const float g = s_g[li];
        acc.x += mx0 + g * (fm.x - mx0);
        acc.y += mx1 + g * (fm.y - mx1);
    }

    float2* outp = (float2*)&g_part[(chunk * BB + b) * DD];
    outp[tid] = acc;
}

__global__ __launch_bounds__(448)
void head_kernel(const float* __restrict__ W,
                 const float* __restrict__ bias,
                 float* __restrict__ out)
{
    const int b    = blockIdx.x;
    const int tid  = threadIdx.x;
    const int wid  = tid >> 5;
    const int lane = tid & 31;

    __shared__ float sx[DD];
    __shared__ float sh[CC];

    // Reduce the 8 partials -> X[b][:]  (150 float2 lanes)
    if (tid < 150) {
        float2 s = make_float2(0.f, 0.f);
        #pragma unroll
        for (int c = 0; c < NCHUNK; ++c) {
            const float2 p = *(const float2*)&g_part[(c * BB + b) * DD + tid * 2];
            s.x += p.x;
            s.y += p.y;
        }
        sx[tid * 2]     = s.x;
        sx[tid * 2 + 1] = s.y;
    }
    __syncthreads();

    // One warp per class: h[c] = relu(X . W[c] + bias[c])
    if (wid < CC) {
        float s = 0.f;
        #pragma unroll
        for (int it = 0; it < 10; ++it) {
            const int d = lane + it * 32;
            if (d < DD) s += sx[d] * W[wid * DD + d];
        }
        #pragma unroll
        for (int off = 16; off; off >>= 1)
            s += __shfl_down_sync(0xffffffffu, s, off);
        if (lane == 0)
            sh[wid] = fmaxf(s + bias[wid], 0.f);
    }
    __syncthreads();

    // Parallel softmax over 14 classes (warp 0)
    if (wid == 0) {
        const float h = (lane < CC) ? sh[lane] : -1e30f;
        float m = h;
        #pragma unroll
        for (int off = 16; off; off >>= 1)
            m = fmaxf(m, __shfl_xor_sync(0xffffffffu, m, off));
        const float e = (lane < CC) ? expf(h - m) : 0.f;
        float sum = e;
        #pragma unroll
        for (int off = 16; off; off >>= 1)
            sum += __shfl_xor_sync(0xffffffffu, sum, off);
        if (lane < CC)
            out[b * CC + lane] = e / sum;
    }
}

extern "C" void kernel_launch(void* const* d_in, const int* in_sizes, int n_in,
                              void* d_out, int out_size)
{
    const int*   master = (const int*)  d_in[0];
    const int*   slave  = (const int*)  d_in[1];
    const int*   edge   = (const int*)  d_in[2];
    const float* R      = (const float*)d_in[3];
    const float* E      = (const float*)d_in[4];
    const float* Ngate  = (const float*)d_in[5];
    const float* W      = (const float*)d_in[6];
    const float* bias   = (const float*)d_in[7];
    float* out = (float*)d_out;

    convert_kernel<<<(NROWS + CVT_ROWS - 1) / CVT_ROWS, 160>>>(R);
    gnn_pool_kernel<<<dim3(NCHUNK, BB), 160>>>(master, slave, edge, E, Ngate);
    head_kernel<<<BB, 448>>>(W, bias, out);
}